// round 3
// baseline (speedup 1.0000x reference)
#include <cuda_runtime.h>
#include <math_constants.h>

#define WSZ    8
#define P2     64
#define CH     128
#define W1G    32
#define NWPB   1024
#define BATCH  8
#define NWIN   (BATCH*NWPB)
#define HD     32
#define NH     4
#define SHIFT  4
#define STR    132          // padded smem row stride (16B aligned, conflict-free for f4)
#define NTHR   512

// ---------------- scratch ----------------
__device__ float g_xw [(size_t)NWIN * P2 * CH];
__device__ float g_off[NWIN * P2 * 2];
__device__ float g_oi [NWIN * 2];
// transposed weights: [co][ci]
__device__ float g_qwT[CH * CH];
__device__ float g_kwT[CH * CH];
__device__ float g_vwT[CH * CH];
__device__ float g_owT[CH * CH];

// ---------------- kernel 0: weight transpose (one-time, tiny) ----------------
__global__ __launch_bounds__(256)
void k_wt(const float* __restrict__ q_w, const float* __restrict__ kv_w,
          const float* __restrict__ o_w)
{
    const int i = blockIdx.x * 256 + threadIdx.x;   // 16384
    const int ci = i >> 7, co = i & 127;
    g_qwT[co * CH + ci] = q_w[ci * CH + co];
    g_kwT[co * CH + ci] = kv_w[ci * 256 + co];
    g_vwT[co * CH + ci] = kv_w[ci * 256 + 128 + co];
    g_owT[co * CH + ci] = o_w[ci * CH + co];
}

// ---------------- kernel 1: window gather + offset MLPs ----------------
__global__ __launch_bounds__(256)
void k_prep(const float* __restrict__ x,
            const float* __restrict__ wi_w, const float* __restrict__ wi_b,
            const float* __restrict__ w1_w, const float* __restrict__ w1_b,
            const float* __restrict__ w2_w, const float* __restrict__ w2_b)
{
    __shared__ float sT[P2 * STR];
    __shared__ float sT1[P2 * 2];

    const int win = blockIdx.x;
    const int b   = win >> 10;
    const int wr  = win & 1023;
    const int wi  = wr >> 5;
    const int wj  = wr & 31;
    const int tid = threadIdx.x;

    float4* gx4 = (float4*)(g_xw + (size_t)win * P2 * CH);

    // gather shifted window, vectorized
    for (int i4 = tid; i4 < P2 * CH / 4; i4 += 256) {
        const int tok = i4 >> 5, c4 = i4 & 31;
        const int pi = tok >> 3, pj = tok & 7;
        const int r = (wi * 8 + pi + SHIFT) & 255;
        const int c = (wj * 8 + pj + SHIFT) & 255;
        const float4 v = *(const float4*)(x + (size_t)((((b << 8) + r) << 8) + c) * CH + c4 * 4);
        *(float4*)(sT + tok * STR + c4 * 4) = v;
        gx4[i4] = v;
    }
    __syncthreads();

    {
        const int kind = tid >> 7;
        const int rem  = tid & 127;
        const int tok  = rem >> 1;
        const int d    = rem & 1;
        const float* w = kind ? w1_w : wi_w;
        float acc = 0.f;
        #pragma unroll 8
        for (int ch = 0; ch < 128; ++ch)
            acc = fmaf(sT[tok * STR + ch], w[ch * 2 + d], acc);
        if (kind) sT1[tok * 2 + d] = acc + w1_b[d];
        else      g_off[win * 128 + tok * 2 + d] = acc + wi_b[d];
    }
    __syncthreads();

    if (tid < 2) {
        float acc = w2_b[tid];
        for (int f = 0; f < 128; ++f)
            acc = fmaf(sT1[f], w2_w[f * 2 + tid], acc);
        g_oi[win * 2 + tid] = acc;
    }
}

// 64x128 GEMM with transposed weights. warp wp: rows g*8..g*8+7, cols hs*64+tx{,+32}.
// Per 4-k chunk: 8 LDS.128 + 2 LDG.128 + 64 FMA.
__device__ __forceinline__
void gemm_t(const float* __restrict__ in_s, const float* __restrict__ wT,
            const float* __restrict__ bias, int boff,
            float* __restrict__ out_s, int g, int hs, int tx)
{
    const int co = hs * 64 + tx;
    float acc[8][2] = {};
    const float4* w0p = (const float4*)(wT + co * CH);
    const float4* w1p = (const float4*)(wT + (co + 32) * CH);
    const float* arow = in_s + (g * 8) * STR;
    #pragma unroll 2
    for (int c4 = 0; c4 < 32; ++c4) {
        const float4 w0 = __ldg(w0p + c4);
        const float4 w1 = __ldg(w1p + c4);
        #pragma unroll
        for (int r = 0; r < 8; ++r) {
            const float4 a = *(const float4*)(arow + r * STR + c4 * 4);
            acc[r][0] = fmaf(a.x, w0.x, acc[r][0]);
            acc[r][0] = fmaf(a.y, w0.y, acc[r][0]);
            acc[r][0] = fmaf(a.z, w0.z, acc[r][0]);
            acc[r][0] = fmaf(a.w, w0.w, acc[r][0]);
            acc[r][1] = fmaf(a.x, w1.x, acc[r][1]);
            acc[r][1] = fmaf(a.y, w1.y, acc[r][1]);
            acc[r][1] = fmaf(a.z, w1.z, acc[r][1]);
            acc[r][1] = fmaf(a.w, w1.w, acc[r][1]);
        }
    }
    const float b0 = bias[boff + co], b1 = bias[boff + co + 32];
    #pragma unroll
    for (int r = 0; r < 8; ++r) {
        out_s[(g * 8 + r) * STR + co]      = acc[r][0] + b0;
        out_s[(g * 8 + r) * STR + co + 32] = acc[r][1] + b1;
    }
}

// ---------------- kernel 2 ----------------
__global__ __launch_bounds__(NTHR)
void k_main(const float* __restrict__ rpp,
            const float* __restrict__ q_b, const float* __restrict__ kv_b,
            const float* __restrict__ o_b, float* __restrict__ out)
{
    extern __shared__ float sm[];
    float* sA   = sm;                   // xd -> xw -> k
    float* sB   = sA + P2 * STR;        // xd2 -> attn-out
    float* sC   = sB + P2 * STR;        // q
    float* sD   = sC + P2 * STR;        // v
    float* sSim = sD + P2 * STR;        // 64x64
    float* sW   = sSim + 4096;
    int*   sIdx = (int*)(sW + 256);

    const int win = blockIdx.x;
    const int b   = win >> 10;
    const int wr  = win & 1023;
    const int wi  = wr >> 5;
    const int wj  = wr & 31;
    const int tid = threadIdx.x;
    const int wp  = tid >> 5, tx = tid & 31;
    const int g   = wp >> 1, hs = wp & 1;

    // ---- inter-window bilinear blend -> sA (xd), vectorized ----
    {
        const float ox = g_oi[win * 2 + 0], oy = g_oi[win * 2 + 1];
        const float gxp = (float)wj + ox, gyp = (float)wi + oy;
        const float x0f = floorf(gxp), y0f = floorf(gyp);
        const float fx = gxp - x0f, fy = gyp - y0f;
        const int x0 = (int)x0f, y0 = (int)y0f;
        const float wgt[4] = {(1.f - fx) * (1.f - fy), fx * (1.f - fy),
                              (1.f - fx) * fy,          fx * fy};
        const float4* nb[4];
        float nww[4];
        #pragma unroll
        for (int k = 0; k < 4; ++k) {
            const int xx = x0 + (k & 1), yy = y0 + (k >> 1);
            const bool valid = (xx >= 0) && (xx < W1G) && (yy >= 0) && (yy < W1G);
            nb[k]  = (const float4*)(valid ? (g_xw + (size_t)((b << 10) + (yy << 5) + xx) * P2 * CH)
                                           : g_xw);
            nww[k] = valid ? wgt[k] : 0.f;
        }
        for (int i4 = tid; i4 < P2 * CH / 4; i4 += NTHR) {
            const float4 v0 = __ldg(nb[0] + i4), v1 = __ldg(nb[1] + i4);
            const float4 v2 = __ldg(nb[2] + i4), v3 = __ldg(nb[3] + i4);
            float4 r;
            r.x = nww[0]*v0.x + nww[1]*v1.x + nww[2]*v2.x + nww[3]*v3.x;
            r.y = nww[0]*v0.y + nww[1]*v1.y + nww[2]*v2.y + nww[3]*v3.y;
            r.z = nww[0]*v0.z + nww[1]*v1.z + nww[2]*v2.z + nww[3]*v3.z;
            r.w = nww[0]*v0.w + nww[1]*v1.w + nww[2]*v2.w + nww[3]*v3.w;
            *(float4*)(sA + (i4 >> 5) * STR + (i4 & 31) * 4) = r;
        }
    }
    if (tid < 64) {
        const int tok = tid, pi = tok >> 3, pj = tok & 7;
        const float o0 = g_off[win * 128 + tok * 2], o1 = g_off[win * 128 + tok * 2 + 1];
        const float gx2 = (float)pj + o0, gy2 = (float)pi + o1;
        const float xf = floorf(gx2), yf = floorf(gy2);
        const float fx = gx2 - xf, fy = gy2 - yf;
        const int x0 = (int)xf, y0 = (int)yf;
        const float ww[4] = {(1.f - fx) * (1.f - fy), fx * (1.f - fy),
                             (1.f - fx) * fy,          fx * fy};
        #pragma unroll
        for (int k = 0; k < 4; ++k) {
            const int xx = x0 + (k & 1), yy = y0 + (k >> 1);
            const bool valid = (xx >= 0) && (xx < WSZ) && (yy >= 0) && (yy < WSZ);
            sIdx[tok * 4 + k] = valid ? (yy * 8 + xx) : 0;
            sW[tok * 4 + k]   = valid ? ww[k] : 0.f;
        }
    }
    __syncthreads();

    // ---- intra-window gather -> sB (xd2), vectorized ----
    for (int i4 = tid; i4 < P2 * CH / 4; i4 += NTHR) {
        const int tok = i4 >> 5, c4 = i4 & 31;
        const int i0 = sIdx[tok * 4 + 0], i1 = sIdx[tok * 4 + 1];
        const int i2 = sIdx[tok * 4 + 2], i3 = sIdx[tok * 4 + 3];
        const float w0 = sW[tok * 4 + 0], w1 = sW[tok * 4 + 1];
        const float w2 = sW[tok * 4 + 2], w3 = sW[tok * 4 + 3];
        const float4 a0 = *(const float4*)(sA + i0 * STR + c4 * 4);
        const float4 a1 = *(const float4*)(sA + i1 * STR + c4 * 4);
        const float4 a2 = *(const float4*)(sA + i2 * STR + c4 * 4);
        const float4 a3 = *(const float4*)(sA + i3 * STR + c4 * 4);
        float4 r;
        r.x = w0*a0.x + w1*a1.x + w2*a2.x + w3*a3.x;
        r.y = w0*a0.y + w1*a1.y + w2*a2.y + w3*a3.y;
        r.z = w0*a0.z + w1*a1.z + w2*a2.z + w3*a3.z;
        r.w = w0*a0.w + w1*a1.w + w2*a2.w + w3*a3.w;
        *(float4*)(sB + tok * STR + c4 * 4) = r;
    }
    __syncthreads();

    // ---- own window xw -> sA, vectorized ----
    {
        const float4* gx4 = (const float4*)(g_xw + (size_t)win * P2 * CH);
        for (int i4 = tid; i4 < P2 * CH / 4; i4 += NTHR)
            *(float4*)(sA + (i4 >> 5) * STR + (i4 & 31) * 4) = __ldg(gx4 + i4);
    }
    __syncthreads();

    // ---- q = xw @ q_w -> sC ----
    gemm_t(sA, g_qwT, q_b, 0, sC, g, hs, tx);
    __syncthreads();
    // ---- k -> sA ; v -> sD (both from xd2 in sB) ----
    gemm_t(sB, g_kwT, kv_b, 0,   sA, g, hs, tx);
    gemm_t(sB, g_vwT, kv_b, 128, sD, g, hs, tx);
    __syncthreads();

    // ---- attention: each warp owns 4 query rows ----
    const float scale = 0.17677669529663687f;
    const bool lastRow = (wi == W1G - 1), lastCol = (wj == W1G - 1);
    const int r0 = wp * 4;
    for (int hh = 0; hh < NH; ++hh) {
        float acc[4][2] = {};
        const float4* qp  = (const float4*)(sC + r0 * STR + hh * HD);
        const float4* k0p = (const float4*)(sA + tx * STR + hh * HD);
        const float4* k1p = (const float4*)(sA + (tx + 32) * STR + hh * HD);
        #pragma unroll
        for (int d4 = 0; d4 < HD / 4; ++d4) {
            const float4 kk0 = k0p[d4], kk1 = k1p[d4];
            #pragma unroll
            for (int r = 0; r < 4; ++r) {
                const float4 qq = *(const float4*)((const float*)qp + r * STR + d4 * 4);
                acc[r][0] = fmaf(qq.x, kk0.x, acc[r][0]);
                acc[r][0] = fmaf(qq.y, kk0.y, acc[r][0]);
                acc[r][0] = fmaf(qq.z, kk0.z, acc[r][0]);
                acc[r][0] = fmaf(qq.w, kk0.w, acc[r][0]);
                acc[r][1] = fmaf(qq.x, kk1.x, acc[r][1]);
                acc[r][1] = fmaf(qq.y, kk1.y, acc[r][1]);
                acc[r][1] = fmaf(qq.z, kk1.z, acc[r][1]);
                acc[r][1] = fmaf(qq.w, kk1.w, acc[r][1]);
            }
        }
        const float* rb = rpp + hh * 225;
        #pragma unroll
        for (int r = 0; r < 4; ++r) {
            const int i = r0 + r, pi_i = i >> 3, pj_i = i & 7;
            #pragma unroll
            for (int u = 0; u < 2; ++u) {
                const int j = tx + 32 * u, pi_j = j >> 3, pj_j = j & 7;
                const float bias = rb[(pi_i - pi_j + 7) * 15 + (pj_i - pj_j + 7)];
                const bool msk = (lastRow && ((pi_i < 4) != (pi_j < 4)))
                              || (lastCol && ((pj_i < 4) != (pj_j < 4)));
                sSim[i * 64 + j] = msk ? -CUDART_INF_F : fmaf(acc[r][u], scale, bias);
            }
        }
        __syncwarp();
        #pragma unroll
        for (int r = 0; r < 4; ++r) {
            const int i = r0 + r;
            const float a = sSim[i * 64 + tx], bb = sSim[i * 64 + tx + 32];
            float m = fmaxf(a, bb);
            #pragma unroll
            for (int s2 = 16; s2 > 0; s2 >>= 1) m = fmaxf(m, __shfl_xor_sync(0xffffffffu, m, s2));
            const float e0 = __expf(a - m), e1 = __expf(bb - m);
            float s = e0 + e1;
            #pragma unroll
            for (int s2 = 16; s2 > 0; s2 >>= 1) s += __shfl_xor_sync(0xffffffffu, s, s2);
            const float inv = 1.f / s;
            sSim[i * 64 + tx]      = e0 * inv;
            sSim[i * 64 + tx + 32] = e1 * inv;
        }
        __syncwarp();
        float po[4] = {};
        #pragma unroll 4
        for (int j = 0; j < 64; ++j) {
            const float vv = sD[j * STR + hh * HD + tx];
            #pragma unroll
            for (int r = 0; r < 4; ++r)
                po[r] = fmaf(sSim[(r0 + r) * 64 + j], vv, po[r]);
        }
        #pragma unroll
        for (int r = 0; r < 4; ++r)
            sB[(r0 + r) * STR + hh * HD + tx] = po[r];
        __syncwarp();
    }
    __syncthreads();

    // ---- o projection + un-shift scatter ----
    {
        const int co = hs * 64 + tx;
        float acc[8][2] = {};
        const float4* w0p = (const float4*)(g_owT + co * CH);
        const float4* w1p = (const float4*)(g_owT + (co + 32) * CH);
        const float* arow = sB + (g * 8) * STR;
        #pragma unroll 2
        for (int c4 = 0; c4 < 32; ++c4) {
            const float4 w0 = __ldg(w0p + c4);
            const float4 w1 = __ldg(w1p + c4);
            #pragma unroll
            for (int r = 0; r < 8; ++r) {
                const float4 a = *(const float4*)(arow + r * STR + c4 * 4);
                acc[r][0] = fmaf(a.x, w0.x, acc[r][0]);
                acc[r][0] = fmaf(a.y, w0.y, acc[r][0]);
                acc[r][0] = fmaf(a.z, w0.z, acc[r][0]);
                acc[r][0] = fmaf(a.w, w0.w, acc[r][0]);
                acc[r][1] = fmaf(a.x, w1.x, acc[r][1]);
                acc[r][1] = fmaf(a.y, w1.y, acc[r][1]);
                acc[r][1] = fmaf(a.z, w1.z, acc[r][1]);
                acc[r][1] = fmaf(a.w, w1.w, acc[r][1]);
            }
        }
        const float b0 = o_b[co], b1 = o_b[co + 32];
        #pragma unroll
        for (int r = 0; r < 8; ++r) {
            const int tok = g * 8 + r, pi = tok >> 3, pj = tok & 7;
            const int rr = (wi * 8 + pi + SHIFT) & 255;
            const int cc = (wj * 8 + pj + SHIFT) & 255;
            float* op = out + (size_t)((((b << 8) + rr) << 8) + cc) * CH;
            op[co]      = acc[r][0] + b0;
            op[co + 32] = acc[r][1] + b1;
        }
    }
}

extern "C" void kernel_launch(void* const* d_in, const int* in_sizes, int n_in,
                              void* d_out, int out_size)
{
    const float* x    = (const float*)d_in[0];
    const float* rpp  = (const float*)d_in[1];
    const float* wi_w = (const float*)d_in[2];
    const float* wi_b = (const float*)d_in[3];
    const float* w1_w = (const float*)d_in[4];
    const float* w1_b = (const float*)d_in[5];
    const float* w2_w = (const float*)d_in[6];
    const float* w2_b = (const float*)d_in[7];
    const float* q_w  = (const float*)d_in[8];
    const float* q_b  = (const float*)d_in[9];
    const float* kv_w = (const float*)d_in[10];
    const float* kv_b = (const float*)d_in[11];
    const float* o_w  = (const float*)d_in[12];
    const float* o_b  = (const float*)d_in[13];
    float* out = (float*)d_out;

    const size_t smem2 = (size_t)(4 * P2 * STR + 4096 + 256 + 256) * sizeof(float);
    cudaFuncSetAttribute(k_main, cudaFuncAttributeMaxDynamicSharedMemorySize, (int)smem2);

    k_wt<<<64, 256>>>(q_w, kv_w, o_w);
    k_prep<<<NWIN, 256>>>(x, wi_w, wi_b, w1_w, w1_b, w2_w, w2_b);
    k_main<<<NWIN, NTHR, smem2>>>(rpp, q_b, kv_b, o_b, out);
}

// round 4
// speedup vs baseline: 1.5030x; 1.5030x over previous
#include <cuda_runtime.h>
#include <math_constants.h>

#define WSZ    8
#define P2     64
#define CH     128
#define W1G    32
#define NWPB   1024
#define BATCH  8
#define NWIN   (BATCH*NWPB)
#define HD     32
#define NH     4
#define SHIFT  4
#define STR    132          // padded smem row stride (16B aligned, conflict-free for f4)
#define NTHR   512

// ---------------- scratch ----------------
__device__ float g_xw [(size_t)NWIN * P2 * CH];
__device__ float g_off[NWIN * P2 * 2];
__device__ float g_oi [NWIN * 2];

// ---------------- kernel 1: window gather + offset MLPs ----------------
__global__ __launch_bounds__(256)
void k_prep(const float* __restrict__ x,
            const float* __restrict__ wi_w, const float* __restrict__ wi_b,
            const float* __restrict__ w1_w, const float* __restrict__ w1_b,
            const float* __restrict__ w2_w, const float* __restrict__ w2_b)
{
    __shared__ float sT[P2 * STR];
    __shared__ float sT1[P2 * 2];

    const int win = blockIdx.x;
    const int b   = win >> 10;
    const int wr  = win & 1023;
    const int wi  = wr >> 5;
    const int wj  = wr & 31;
    const int tid = threadIdx.x;

    float4* gx4 = (float4*)(g_xw + (size_t)win * P2 * CH);

    for (int i4 = tid; i4 < P2 * CH / 4; i4 += 256) {
        const int tok = i4 >> 5, c4 = i4 & 31;
        const int pi = tok >> 3, pj = tok & 7;
        const int r = (wi * 8 + pi + SHIFT) & 255;
        const int c = (wj * 8 + pj + SHIFT) & 255;
        const float4 v = *(const float4*)(x + (size_t)((((b << 8) + r) << 8) + c) * CH + c4 * 4);
        *(float4*)(sT + tok * STR + c4 * 4) = v;
        gx4[i4] = v;
    }
    __syncthreads();

    {
        const int kind = tid >> 7;
        const int rem  = tid & 127;
        const int tok  = rem >> 1;
        const int d    = rem & 1;
        const float* w = kind ? w1_w : wi_w;
        float acc = 0.f;
        #pragma unroll 8
        for (int ch = 0; ch < 128; ++ch)
            acc = fmaf(sT[tok * STR + ch], w[ch * 2 + d], acc);
        if (kind) sT1[tok * 2 + d] = acc + w1_b[d];
        else      g_off[win * 128 + tok * 2 + d] = acc + wi_b[d];
    }
    __syncthreads();

    if (tid < 2) {
        float acc = w2_b[tid];
        for (int f = 0; f < 128; ++f)
            acc = fmaf(sT1[f], w2_w[f * 2 + tid], acc);
        g_oi[win * 2 + tid] = acc;
    }
}

// 64x128 GEMM, weights in native [ci][co] layout.
// warp wp: rows wp*4..wp*4+3; lane tx: cols 4tx..4tx+3 (coalesced float4 W loads).
// Per 4-k chunk: 4 LDS.128 (broadcast A) + 4 LDG.128 (coalesced W) + 64 FMA.
__device__ __forceinline__
void gemm_v(const float* __restrict__ in_s, const float* __restrict__ w,
            int wstride, int woff, const float* __restrict__ bias, int boff,
            float* __restrict__ out_s, int wp, int tx)
{
    float acc[4][4] = {};
    const float* arow = in_s + (wp * 4) * STR;
    const float* wbase = w + woff + tx * 4;
    #pragma unroll 4
    for (int ci = 0; ci < 128; ++ci) {
        const float4 wv = __ldg((const float4*)(wbase + (size_t)ci * wstride));
        const float a0 = arow[0 * STR + ci];
        const float a1 = arow[1 * STR + ci];
        const float a2 = arow[2 * STR + ci];
        const float a3 = arow[3 * STR + ci];
        acc[0][0] = fmaf(a0, wv.x, acc[0][0]); acc[0][1] = fmaf(a0, wv.y, acc[0][1]);
        acc[0][2] = fmaf(a0, wv.z, acc[0][2]); acc[0][3] = fmaf(a0, wv.w, acc[0][3]);
        acc[1][0] = fmaf(a1, wv.x, acc[1][0]); acc[1][1] = fmaf(a1, wv.y, acc[1][1]);
        acc[1][2] = fmaf(a1, wv.z, acc[1][2]); acc[1][3] = fmaf(a1, wv.w, acc[1][3]);
        acc[2][0] = fmaf(a2, wv.x, acc[2][0]); acc[2][1] = fmaf(a2, wv.y, acc[2][1]);
        acc[2][2] = fmaf(a2, wv.z, acc[2][2]); acc[2][3] = fmaf(a2, wv.w, acc[2][3]);
        acc[3][0] = fmaf(a3, wv.x, acc[3][0]); acc[3][1] = fmaf(a3, wv.y, acc[3][1]);
        acc[3][2] = fmaf(a3, wv.z, acc[3][2]); acc[3][3] = fmaf(a3, wv.w, acc[3][3]);
    }
    const float4 bv = *(const float4*)(bias + boff + tx * 4);
    #pragma unroll
    for (int r = 0; r < 4; ++r) {
        float4 o;
        o.x = acc[r][0] + bv.x; o.y = acc[r][1] + bv.y;
        o.z = acc[r][2] + bv.z; o.w = acc[r][3] + bv.w;
        *(float4*)(out_s + (wp * 4 + r) * STR + tx * 4) = o;
    }
}

// ---------------- kernel 2 ----------------
__global__ __launch_bounds__(NTHR)
void k_main(const float* __restrict__ rpp,
            const float* __restrict__ q_w,  const float* __restrict__ q_b,
            const float* __restrict__ kv_w, const float* __restrict__ kv_b,
            const float* __restrict__ o_w,  const float* __restrict__ o_b,
            float* __restrict__ out)
{
    extern __shared__ float sm[];
    float* sA   = sm;                   // xd -> xw -> k
    float* sB   = sA + P2 * STR;        // xd2 -> attn-out
    float* sC   = sB + P2 * STR;        // q
    float* sD   = sC + P2 * STR;        // v
    float* sSim = sD + P2 * STR;        // 64x64
    float* sW   = sSim + 4096;
    int*   sIdx = (int*)(sW + 256);

    const int win = blockIdx.x;
    const int b   = win >> 10;
    const int wr  = win & 1023;
    const int wi  = wr >> 5;
    const int wj  = wr & 31;
    const int tid = threadIdx.x;
    const int wp  = tid >> 5, tx = tid & 31;

    // ---- inter-window bilinear blend -> sA (xd) ----
    {
        const float ox = g_oi[win * 2 + 0], oy = g_oi[win * 2 + 1];
        const float gxp = (float)wj + ox, gyp = (float)wi + oy;
        const float x0f = floorf(gxp), y0f = floorf(gyp);
        const float fx = gxp - x0f, fy = gyp - y0f;
        const int x0 = (int)x0f, y0 = (int)y0f;
        const float wgt[4] = {(1.f - fx) * (1.f - fy), fx * (1.f - fy),
                              (1.f - fx) * fy,          fx * fy};
        const float4* nb[4];
        float nww[4];
        #pragma unroll
        for (int k = 0; k < 4; ++k) {
            const int xx = x0 + (k & 1), yy = y0 + (k >> 1);
            const bool valid = (xx >= 0) && (xx < W1G) && (yy >= 0) && (yy < W1G);
            nb[k]  = (const float4*)(valid ? (g_xw + (size_t)((b << 10) + (yy << 5) + xx) * P2 * CH)
                                           : g_xw);
            nww[k] = valid ? wgt[k] : 0.f;
        }
        for (int i4 = tid; i4 < P2 * CH / 4; i4 += NTHR) {
            const float4 v0 = __ldg(nb[0] + i4), v1 = __ldg(nb[1] + i4);
            const float4 v2 = __ldg(nb[2] + i4), v3 = __ldg(nb[3] + i4);
            float4 r;
            r.x = nww[0]*v0.x + nww[1]*v1.x + nww[2]*v2.x + nww[3]*v3.x;
            r.y = nww[0]*v0.y + nww[1]*v1.y + nww[2]*v2.y + nww[3]*v3.y;
            r.z = nww[0]*v0.z + nww[1]*v1.z + nww[2]*v2.z + nww[3]*v3.z;
            r.w = nww[0]*v0.w + nww[1]*v1.w + nww[2]*v2.w + nww[3]*v3.w;
            *(float4*)(sA + (i4 >> 5) * STR + (i4 & 31) * 4) = r;
        }
    }
    if (tid < 64) {
        const int tok = tid, pi = tok >> 3, pj = tok & 7;
        const float o0 = g_off[win * 128 + tok * 2], o1 = g_off[win * 128 + tok * 2 + 1];
        const float gx2 = (float)pj + o0, gy2 = (float)pi + o1;
        const float xf = floorf(gx2), yf = floorf(gy2);
        const float fx = gx2 - xf, fy = gy2 - yf;
        const int x0 = (int)xf, y0 = (int)yf;
        const float ww[4] = {(1.f - fx) * (1.f - fy), fx * (1.f - fy),
                             (1.f - fx) * fy,          fx * fy};
        #pragma unroll
        for (int k = 0; k < 4; ++k) {
            const int xx = x0 + (k & 1), yy = y0 + (k >> 1);
            const bool valid = (xx >= 0) && (xx < WSZ) && (yy >= 0) && (yy < WSZ);
            sIdx[tok * 4 + k] = valid ? (yy * 8 + xx) : 0;
            sW[tok * 4 + k]   = valid ? ww[k] : 0.f;
        }
    }
    __syncthreads();

    // ---- intra-window gather -> sB (xd2) ----
    for (int i4 = tid; i4 < P2 * CH / 4; i4 += NTHR) {
        const int tok = i4 >> 5, c4 = i4 & 31;
        const int i0 = sIdx[tok * 4 + 0], i1 = sIdx[tok * 4 + 1];
        const int i2 = sIdx[tok * 4 + 2], i3 = sIdx[tok * 4 + 3];
        const float w0 = sW[tok * 4 + 0], w1 = sW[tok * 4 + 1];
        const float w2 = sW[tok * 4 + 2], w3 = sW[tok * 4 + 3];
        const float4 a0 = *(const float4*)(sA + i0 * STR + c4 * 4);
        const float4 a1 = *(const float4*)(sA + i1 * STR + c4 * 4);
        const float4 a2 = *(const float4*)(sA + i2 * STR + c4 * 4);
        const float4 a3 = *(const float4*)(sA + i3 * STR + c4 * 4);
        float4 r;
        r.x = w0*a0.x + w1*a1.x + w2*a2.x + w3*a3.x;
        r.y = w0*a0.y + w1*a1.y + w2*a2.y + w3*a3.y;
        r.z = w0*a0.z + w1*a1.z + w2*a2.z + w3*a3.z;
        r.w = w0*a0.w + w1*a1.w + w2*a2.w + w3*a3.w;
        *(float4*)(sB + tok * STR + c4 * 4) = r;
    }
    __syncthreads();

    // ---- own window xw -> sA ----
    {
        const float4* gx4 = (const float4*)(g_xw + (size_t)win * P2 * CH);
        for (int i4 = tid; i4 < P2 * CH / 4; i4 += NTHR)
            *(float4*)(sA + (i4 >> 5) * STR + (i4 & 31) * 4) = __ldg(gx4 + i4);
    }
    __syncthreads();

    // ---- q = xw @ q_w -> sC ----
    gemm_v(sA, q_w, 128, 0, q_b, 0, sC, wp, tx);
    __syncthreads();
    // ---- k -> sA ; v -> sD (both from xd2 in sB) ----
    gemm_v(sB, kv_w, 256, 0,   kv_b, 0,   sA, wp, tx);
    gemm_v(sB, kv_w, 256, 128, kv_b, 128, sD, wp, tx);
    __syncthreads();

    // ---- attention: each warp owns 4 query rows (r0 = wp*4) ----
    const float scale = 0.17677669529663687f;
    const bool lastRow = (wi == W1G - 1), lastCol = (wj == W1G - 1);
    const int r0 = wp * 4;
    for (int hh = 0; hh < NH; ++hh) {
        float acc[4][2] = {};
        const float* qp   = sC + r0 * STR + hh * HD;
        const float4* k0p = (const float4*)(sA + tx * STR + hh * HD);
        const float4* k1p = (const float4*)(sA + (tx + 32) * STR + hh * HD);
        #pragma unroll
        for (int d4 = 0; d4 < HD / 4; ++d4) {
            const float4 kk0 = k0p[d4], kk1 = k1p[d4];
            #pragma unroll
            for (int r = 0; r < 4; ++r) {
                const float4 qq = *(const float4*)(qp + r * STR + d4 * 4);
                acc[r][0] = fmaf(qq.x, kk0.x, acc[r][0]);
                acc[r][0] = fmaf(qq.y, kk0.y, acc[r][0]);
                acc[r][0] = fmaf(qq.z, kk0.z, acc[r][0]);
                acc[r][0] = fmaf(qq.w, kk0.w, acc[r][0]);
                acc[r][1] = fmaf(qq.x, kk1.x, acc[r][1]);
                acc[r][1] = fmaf(qq.y, kk1.y, acc[r][1]);
                acc[r][1] = fmaf(qq.z, kk1.z, acc[r][1]);
                acc[r][1] = fmaf(qq.w, kk1.w, acc[r][1]);
            }
        }
        const float* rb = rpp + hh * 225;
        #pragma unroll
        for (int r = 0; r < 4; ++r) {
            const int i = r0 + r, pi_i = i >> 3, pj_i = i & 7;
            #pragma unroll
            for (int u = 0; u < 2; ++u) {
                const int j = tx + 32 * u, pi_j = j >> 3, pj_j = j & 7;
                const float bias = rb[(pi_i - pi_j + 7) * 15 + (pj_i - pj_j + 7)];
                const bool msk = (lastRow && ((pi_i < 4) != (pi_j < 4)))
                              || (lastCol && ((pj_i < 4) != (pj_j < 4)));
                sSim[i * 64 + j] = msk ? -CUDART_INF_F : fmaf(acc[r][u], scale, bias);
            }
        }
        __syncwarp();
        #pragma unroll
        for (int r = 0; r < 4; ++r) {
            const int i = r0 + r;
            const float a = sSim[i * 64 + tx], bb = sSim[i * 64 + tx + 32];
            float m = fmaxf(a, bb);
            #pragma unroll
            for (int s2 = 16; s2 > 0; s2 >>= 1) m = fmaxf(m, __shfl_xor_sync(0xffffffffu, m, s2));
            const float e0 = __expf(a - m), e1 = __expf(bb - m);
            float s = e0 + e1;
            #pragma unroll
            for (int s2 = 16; s2 > 0; s2 >>= 1) s += __shfl_xor_sync(0xffffffffu, s, s2);
            const float inv = 1.f / s;
            sSim[i * 64 + tx]      = e0 * inv;
            sSim[i * 64 + tx + 32] = e1 * inv;
        }
        __syncwarp();
        float po[4] = {};
        #pragma unroll 4
        for (int j = 0; j < 64; ++j) {
            const float vv = sD[j * STR + hh * HD + tx];
            #pragma unroll
            for (int r = 0; r < 4; ++r)
                po[r] = fmaf(sSim[(r0 + r) * 64 + j], vv, po[r]);
        }
        #pragma unroll
        for (int r = 0; r < 4; ++r)
            sB[(r0 + r) * STR + hh * HD + tx] = po[r];
        __syncwarp();
    }
    __syncthreads();

    // ---- o projection + un-shift scatter (rows wp*4..+3, lane cols 4tx..4tx+3) ----
    {
        float acc[4][4] = {};
        const float* arow = sB + (wp * 4) * STR;
        const float* wbase = o_w + tx * 4;
        #pragma unroll 4
        for (int ci = 0; ci < 128; ++ci) {
            const float4 wv = __ldg((const float4*)(wbase + ci * 128));
            const float a0 = arow[0 * STR + ci];
            const float a1 = arow[1 * STR + ci];
            const float a2 = arow[2 * STR + ci];
            const float a3 = arow[3 * STR + ci];
            acc[0][0] = fmaf(a0, wv.x, acc[0][0]); acc[0][1] = fmaf(a0, wv.y, acc[0][1]);
            acc[0][2] = fmaf(a0, wv.z, acc[0][2]); acc[0][3] = fmaf(a0, wv.w, acc[0][3]);
            acc[1][0] = fmaf(a1, wv.x, acc[1][0]); acc[1][1] = fmaf(a1, wv.y, acc[1][1]);
            acc[1][2] = fmaf(a1, wv.z, acc[1][2]); acc[1][3] = fmaf(a1, wv.w, acc[1][3]);
            acc[2][0] = fmaf(a2, wv.x, acc[2][0]); acc[2][1] = fmaf(a2, wv.y, acc[2][1]);
            acc[2][2] = fmaf(a2, wv.z, acc[2][2]); acc[2][3] = fmaf(a2, wv.w, acc[2][3]);
            acc[3][0] = fmaf(a3, wv.x, acc[3][0]); acc[3][1] = fmaf(a3, wv.y, acc[3][1]);
            acc[3][2] = fmaf(a3, wv.z, acc[3][2]); acc[3][3] = fmaf(a3, wv.w, acc[3][3]);
        }
        const float4 bv = *(const float4*)(o_b + tx * 4);
        #pragma unroll
        for (int r = 0; r < 4; ++r) {
            const int tok = wp * 4 + r, pi = tok >> 3, pj = tok & 7;
            const int rr = (wi * 8 + pi + SHIFT) & 255;
            const int cc = (wj * 8 + pj + SHIFT) & 255;
            float4 o;
            o.x = acc[r][0] + bv.x; o.y = acc[r][1] + bv.y;
            o.z = acc[r][2] + bv.z; o.w = acc[r][3] + bv.w;
            *(float4*)(out + (size_t)((((b << 8) + rr) << 8) + cc) * CH + tx * 4) = o;
        }
    }
}

extern "C" void kernel_launch(void* const* d_in, const int* in_sizes, int n_in,
                              void* d_out, int out_size)
{
    const float* x    = (const float*)d_in[0];
    const float* rpp  = (const float*)d_in[1];
    const float* wi_w = (const float*)d_in[2];
    const float* wi_b = (const float*)d_in[3];
    const float* w1_w = (const float*)d_in[4];
    const float* w1_b = (const float*)d_in[5];
    const float* w2_w = (const float*)d_in[6];
    const float* w2_b = (const float*)d_in[7];
    const float* q_w  = (const float*)d_in[8];
    const float* q_b  = (const float*)d_in[9];
    const float* kv_w = (const float*)d_in[10];
    const float* kv_b = (const float*)d_in[11];
    const float* o_w  = (const float*)d_in[12];
    const float* o_b  = (const float*)d_in[13];
    float* out = (float*)d_out;

    const size_t smem2 = (size_t)(4 * P2 * STR + 4096 + 256 + 256) * sizeof(float);
    cudaFuncSetAttribute(k_main, cudaFuncAttributeMaxDynamicSharedMemorySize, (int)smem2);

    k_prep<<<NWIN, 256>>>(x, wi_w, wi_b, w1_w, w1_b, w2_w, w2_b);
    k_main<<<NWIN, NTHR, smem2>>>(rpp, q_w, q_b, kv_w, kv_b, o_w, o_b, out);
}

// round 5
// speedup vs baseline: 1.7909x; 1.1916x over previous
#include <cuda_runtime.h>
#include <math_constants.h>

#define WSZ    8
#define P2     64
#define CH     128
#define W1G    32
#define NWPB   1024
#define BATCH  8
#define NWIN   (BATCH*NWPB)
#define HD     32
#define NH     4
#define SHIFT  4
#define STR    132
#define NTHR   512

// ---------------- scratch ----------------
__device__ float g_xw [(size_t)NWIN * P2 * CH];
__device__ float g_off[NWIN * P2 * 2];
__device__ float g_oi [NWIN * 2];

// ---------------- kernel 1: window gather + offset MLPs ----------------
__global__ __launch_bounds__(256)
void k_prep(const float* __restrict__ x,
            const float* __restrict__ wi_w, const float* __restrict__ wi_b,
            const float* __restrict__ w1_w, const float* __restrict__ w1_b,
            const float* __restrict__ w2_w, const float* __restrict__ w2_b)
{
    __shared__ float sT[P2 * STR];
    __shared__ float sT1[P2 * 2];

    const int win = blockIdx.x;
    const int b   = win >> 10;
    const int wr  = win & 1023;
    const int wi  = wr >> 5;
    const int wj  = wr & 31;
    const int tid = threadIdx.x;

    float4* gx4 = (float4*)(g_xw + (size_t)win * P2 * CH);

    for (int i4 = tid; i4 < P2 * CH / 4; i4 += 256) {
        const int tok = i4 >> 5, c4 = i4 & 31;
        const int pi = tok >> 3, pj = tok & 7;
        const int r = (wi * 8 + pi + SHIFT) & 255;
        const int c = (wj * 8 + pj + SHIFT) & 255;
        const float4 v = *(const float4*)(x + (size_t)((((b << 8) + r) << 8) + c) * CH + c4 * 4);
        *(float4*)(sT + tok * STR + c4 * 4) = v;
        gx4[i4] = v;
    }
    __syncthreads();

    {
        const int kind = tid >> 7;
        const int rem  = tid & 127;
        const int tok  = rem >> 1;
        const int d    = rem & 1;
        const float* w = kind ? w1_w : wi_w;
        float acc = 0.f;
        #pragma unroll 8
        for (int ch = 0; ch < 128; ++ch)
            acc = fmaf(sT[tok * STR + ch], w[ch * 2 + d], acc);
        if (kind) sT1[tok * 2 + d] = acc + w1_b[d];
        else      g_off[win * 128 + tok * 2 + d] = acc + wi_b[d];
    }
    __syncthreads();

    if (tid < 2) {
        float acc = w2_b[tid];
        for (int f = 0; f < 128; ++f)
            acc = fmaf(sT1[f], w2_w[f * 2 + tid], acc);
        g_oi[win * 2 + tid] = acc;
    }
}

// 64x128 GEMM, 8 active warps: warp g rows g*8..g*8+7; lane tx cols 4tx..4tx+3.
// Per 4-k chunk: 4 LDG.128 (coalesced W) + 8 LDS.128 (broadcast A) + 128 FFMA.
__device__ __forceinline__
void gemm8(const float* __restrict__ in_s, const float* __restrict__ w,
           int wstride, int woff, const float* __restrict__ bias, int boff,
           float* __restrict__ out_s, int g, int tx)
{
    float acc[8][4] = {};
    const float* arow  = in_s + (g * 8) * STR;
    const float* wbase = w + woff + tx * 4;
    #pragma unroll 2
    for (int c4 = 0; c4 < 32; ++c4) {
        const int ci = c4 * 4;
        const float4 w0 = __ldg((const float4*)(wbase + (size_t)(ci + 0) * wstride));
        const float4 w1 = __ldg((const float4*)(wbase + (size_t)(ci + 1) * wstride));
        const float4 w2 = __ldg((const float4*)(wbase + (size_t)(ci + 2) * wstride));
        const float4 w3 = __ldg((const float4*)(wbase + (size_t)(ci + 3) * wstride));
        #pragma unroll
        for (int r = 0; r < 8; ++r) {
            const float4 a = *(const float4*)(arow + r * STR + ci);
            acc[r][0] = fmaf(a.x, w0.x, acc[r][0]);
            acc[r][1] = fmaf(a.x, w0.y, acc[r][1]);
            acc[r][2] = fmaf(a.x, w0.z, acc[r][2]);
            acc[r][3] = fmaf(a.x, w0.w, acc[r][3]);
            acc[r][0] = fmaf(a.y, w1.x, acc[r][0]);
            acc[r][1] = fmaf(a.y, w1.y, acc[r][1]);
            acc[r][2] = fmaf(a.y, w1.z, acc[r][2]);
            acc[r][3] = fmaf(a.y, w1.w, acc[r][3]);
            acc[r][0] = fmaf(a.z, w2.x, acc[r][0]);
            acc[r][1] = fmaf(a.z, w2.y, acc[r][1]);
            acc[r][2] = fmaf(a.z, w2.z, acc[r][2]);
            acc[r][3] = fmaf(a.z, w2.w, acc[r][3]);
            acc[r][0] = fmaf(a.w, w3.x, acc[r][0]);
            acc[r][1] = fmaf(a.w, w3.y, acc[r][1]);
            acc[r][2] = fmaf(a.w, w3.z, acc[r][2]);
            acc[r][3] = fmaf(a.w, w3.w, acc[r][3]);
        }
    }
    const float4 bv = *(const float4*)(bias + boff + tx * 4);
    #pragma unroll
    for (int r = 0; r < 8; ++r) {
        float4 o;
        o.x = acc[r][0] + bv.x; o.y = acc[r][1] + bv.y;
        o.z = acc[r][2] + bv.z; o.w = acc[r][3] + bv.w;
        *(float4*)(out_s + (g * 8 + r) * STR + tx * 4) = o;
    }
}

// ---------------- kernel 2 ----------------
__global__ __launch_bounds__(NTHR)
void k_main(const float* __restrict__ rpp,
            const float* __restrict__ q_w,  const float* __restrict__ q_b,
            const float* __restrict__ kv_w, const float* __restrict__ kv_b,
            const float* __restrict__ o_w,  const float* __restrict__ o_b,
            float* __restrict__ out)
{
    extern __shared__ float sm[];
    float* sA   = sm;                   // xd -> xw -> k
    float* sB   = sA + P2 * STR;        // xd2 -> attn-out
    float* sC   = sB + P2 * STR;        // q
    float* sD   = sC + P2 * STR;        // v
    float* sSim = sD + P2 * STR;        // 64x64
    float* sW   = sSim + 4096;
    int*   sIdx = (int*)(sW + 256);

    const int win = blockIdx.x;
    const int b   = win >> 10;
    const int wr  = win & 1023;
    const int wi  = wr >> 5;
    const int wj  = wr & 31;
    const int tid = threadIdx.x;
    const int wp  = tid >> 5, tx = tid & 31;

    // ---- inter-window bilinear blend -> sA (xd) ----
    {
        const float ox = g_oi[win * 2 + 0], oy = g_oi[win * 2 + 1];
        const float gxp = (float)wj + ox, gyp = (float)wi + oy;
        const float x0f = floorf(gxp), y0f = floorf(gyp);
        const float fx = gxp - x0f, fy = gyp - y0f;
        const int x0 = (int)x0f, y0 = (int)y0f;
        const float wgt[4] = {(1.f - fx) * (1.f - fy), fx * (1.f - fy),
                              (1.f - fx) * fy,          fx * fy};
        const float4* nb[4];
        float nww[4];
        #pragma unroll
        for (int k = 0; k < 4; ++k) {
            const int xx = x0 + (k & 1), yy = y0 + (k >> 1);
            const bool valid = (xx >= 0) && (xx < W1G) && (yy >= 0) && (yy < W1G);
            nb[k]  = (const float4*)(valid ? (g_xw + (size_t)((b << 10) + (yy << 5) + xx) * P2 * CH)
                                           : g_xw);
            nww[k] = valid ? wgt[k] : 0.f;
        }
        for (int i4 = tid; i4 < P2 * CH / 4; i4 += NTHR) {
            const float4 v0 = __ldg(nb[0] + i4), v1 = __ldg(nb[1] + i4);
            const float4 v2 = __ldg(nb[2] + i4), v3 = __ldg(nb[3] + i4);
            float4 r;
            r.x = nww[0]*v0.x + nww[1]*v1.x + nww[2]*v2.x + nww[3]*v3.x;
            r.y = nww[0]*v0.y + nww[1]*v1.y + nww[2]*v2.y + nww[3]*v3.y;
            r.z = nww[0]*v0.z + nww[1]*v1.z + nww[2]*v2.z + nww[3]*v3.z;
            r.w = nww[0]*v0.w + nww[1]*v1.w + nww[2]*v2.w + nww[3]*v3.w;
            *(float4*)(sA + (i4 >> 5) * STR + (i4 & 31) * 4) = r;
        }
    }
    if (tid < 64) {
        const int tok = tid, pi = tok >> 3, pj = tok & 7;
        const float o0 = g_off[win * 128 + tok * 2], o1 = g_off[win * 128 + tok * 2 + 1];
        const float gx2 = (float)pj + o0, gy2 = (float)pi + o1;
        const float xf = floorf(gx2), yf = floorf(gy2);
        const float fx = gx2 - xf, fy = gy2 - yf;
        const int x0 = (int)xf, y0 = (int)yf;
        const float ww[4] = {(1.f - fx) * (1.f - fy), fx * (1.f - fy),
                             (1.f - fx) * fy,          fx * fy};
        #pragma unroll
        for (int k = 0; k < 4; ++k) {
            const int xx = x0 + (k & 1), yy = y0 + (k >> 1);
            const bool valid = (xx >= 0) && (xx < WSZ) && (yy >= 0) && (yy < WSZ);
            sIdx[tok * 4 + k] = valid ? (yy * 8 + xx) : 0;
            sW[tok * 4 + k]   = valid ? ww[k] : 0.f;
        }
    }
    __syncthreads();

    // ---- intra-window gather -> sB (xd2) ----
    for (int i4 = tid; i4 < P2 * CH / 4; i4 += NTHR) {
        const int tok = i4 >> 5, c4 = i4 & 31;
        const int i0 = sIdx[tok * 4 + 0], i1 = sIdx[tok * 4 + 1];
        const int i2 = sIdx[tok * 4 + 2], i3 = sIdx[tok * 4 + 3];
        const float w0 = sW[tok * 4 + 0], w1 = sW[tok * 4 + 1];
        const float w2 = sW[tok * 4 + 2], w3 = sW[tok * 4 + 3];
        const float4 a0 = *(const float4*)(sA + i0 * STR + c4 * 4);
        const float4 a1 = *(const float4*)(sA + i1 * STR + c4 * 4);
        const float4 a2 = *(const float4*)(sA + i2 * STR + c4 * 4);
        const float4 a3 = *(const float4*)(sA + i3 * STR + c4 * 4);
        float4 r;
        r.x = w0*a0.x + w1*a1.x + w2*a2.x + w3*a3.x;
        r.y = w0*a0.y + w1*a1.y + w2*a2.y + w3*a3.y;
        r.z = w0*a0.z + w1*a1.z + w2*a2.z + w3*a3.z;
        r.w = w0*a0.w + w1*a1.w + w2*a2.w + w3*a3.w;
        *(float4*)(sB + tok * STR + c4 * 4) = r;
    }
    __syncthreads();

    // ---- own window xw -> sA ----
    {
        const float4* gx4 = (const float4*)(g_xw + (size_t)win * P2 * CH);
        for (int i4 = tid; i4 < P2 * CH / 4; i4 += NTHR)
            *(float4*)(sA + (i4 >> 5) * STR + (i4 & 31) * 4) = __ldg(gx4 + i4);
    }
    __syncthreads();

    // ---- phase A: q (warps 0-7, sA->sC)  ||  v (warps 8-15, sB->sD) ----
    if (wp < 8) gemm8(sA, q_w, 128, 0, q_b, 0, sC, wp, tx);
    else        gemm8(sB, kv_w, 256, 128, kv_b, 128, sD, wp - 8, tx);
    __syncthreads();
    // ---- phase B: k (warps 0-7, sB->sA) ----
    if (wp < 8) gemm8(sB, kv_w, 256, 0, kv_b, 0, sA, wp, tx);
    __syncthreads();

    // ---- attention: each warp owns 4 query rows (r0 = wp*4) ----
    const float scale = 0.17677669529663687f;
    const bool lastRow = (wi == W1G - 1), lastCol = (wj == W1G - 1);
    const int r0 = wp * 4;
    for (int hh = 0; hh < NH; ++hh) {
        float acc[4][2] = {};
        const float* qp   = sC + r0 * STR + hh * HD;
        const float4* k0p = (const float4*)(sA + tx * STR + hh * HD);
        const float4* k1p = (const float4*)(sA + (tx + 32) * STR + hh * HD);
        #pragma unroll
        for (int d4 = 0; d4 < HD / 4; ++d4) {
            const float4 kk0 = k0p[d4], kk1 = k1p[d4];
            #pragma unroll
            for (int r = 0; r < 4; ++r) {
                const float4 qq = *(const float4*)(qp + r * STR + d4 * 4);
                acc[r][0] = fmaf(qq.x, kk0.x, acc[r][0]);
                acc[r][0] = fmaf(qq.y, kk0.y, acc[r][0]);
                acc[r][0] = fmaf(qq.z, kk0.z, acc[r][0]);
                acc[r][0] = fmaf(qq.w, kk0.w, acc[r][0]);
                acc[r][1] = fmaf(qq.x, kk1.x, acc[r][1]);
                acc[r][1] = fmaf(qq.y, kk1.y, acc[r][1]);
                acc[r][1] = fmaf(qq.z, kk1.z, acc[r][1]);
                acc[r][1] = fmaf(qq.w, kk1.w, acc[r][1]);
            }
        }
        const float* rb = rpp + hh * 225;
        #pragma unroll
        for (int r = 0; r < 4; ++r) {
            const int i = r0 + r, pi_i = i >> 3, pj_i = i & 7;
            #pragma unroll
            for (int u = 0; u < 2; ++u) {
                const int j = tx + 32 * u, pi_j = j >> 3, pj_j = j & 7;
                const float bias = rb[(pi_i - pi_j + 7) * 15 + (pj_i - pj_j + 7)];
                const bool msk = (lastRow && ((pi_i < 4) != (pi_j < 4)))
                              || (lastCol && ((pj_i < 4) != (pj_j < 4)));
                sSim[i * 64 + j] = msk ? -CUDART_INF_F : fmaf(acc[r][u], scale, bias);
            }
        }
        __syncwarp();
        #pragma unroll
        for (int r = 0; r < 4; ++r) {
            const int i = r0 + r;
            const float a = sSim[i * 64 + tx], bb = sSim[i * 64 + tx + 32];
            float m = fmaxf(a, bb);
            #pragma unroll
            for (int s2 = 16; s2 > 0; s2 >>= 1) m = fmaxf(m, __shfl_xor_sync(0xffffffffu, m, s2));
            const float e0 = __expf(a - m), e1 = __expf(bb - m);
            float s = e0 + e1;
            #pragma unroll
            for (int s2 = 16; s2 > 0; s2 >>= 1) s += __shfl_xor_sync(0xffffffffu, s, s2);
            const float inv = 1.f / s;
            sSim[i * 64 + tx]      = e0 * inv;
            sSim[i * 64 + tx + 32] = e1 * inv;
        }
        __syncwarp();
        float po[4] = {};
        #pragma unroll 4
        for (int j = 0; j < 64; ++j) {
            const float vv = sD[j * STR + hh * HD + tx];
            #pragma unroll
            for (int r = 0; r < 4; ++r)
                po[r] = fmaf(sSim[(r0 + r) * 64 + j], vv, po[r]);
        }
        #pragma unroll
        for (int r = 0; r < 4; ++r)
            sB[(r0 + r) * STR + hh * HD + tx] = po[r];
        __syncwarp();
    }
    __syncthreads();

    // ---- o projection (warps 0-7, 8 rows each) + un-shift scatter ----
    if (wp < 8) {
        float acc[8][4] = {};
        const float* arow  = sB + (wp * 8) * STR;
        const float* wbase = o_w + tx * 4;
        #pragma unroll 2
        for (int c4 = 0; c4 < 32; ++c4) {
            const int ci = c4 * 4;
            const float4 w0 = __ldg((const float4*)(wbase + (ci + 0) * 128));
            const float4 w1 = __ldg((const float4*)(wbase + (ci + 1) * 128));
            const float4 w2 = __ldg((const float4*)(wbase + (ci + 2) * 128));
            const float4 w3 = __ldg((const float4*)(wbase + (ci + 3) * 128));
            #pragma unroll
            for (int r = 0; r < 8; ++r) {
                const float4 a = *(const float4*)(arow + r * STR + ci);
                acc[r][0] = fmaf(a.x, w0.x, acc[r][0]);
                acc[r][1] = fmaf(a.x, w0.y, acc[r][1]);
                acc[r][2] = fmaf(a.x, w0.z, acc[r][2]);
                acc[r][3] = fmaf(a.x, w0.w, acc[r][3]);
                acc[r][0] = fmaf(a.y, w1.x, acc[r][0]);
                acc[r][1] = fmaf(a.y, w1.y, acc[r][1]);
                acc[r][2] = fmaf(a.y, w1.z, acc[r][2]);
                acc[r][3] = fmaf(a.y, w1.w, acc[r][3]);
                acc[r][0] = fmaf(a.z, w2.x, acc[r][0]);
                acc[r][1] = fmaf(a.z, w2.y, acc[r][1]);
                acc[r][2] = fmaf(a.z, w2.z, acc[r][2]);
                acc[r][3] = fmaf(a.z, w2.w, acc[r][3]);
                acc[r][0] = fmaf(a.w, w3.x, acc[r][0]);
                acc[r][1] = fmaf(a.w, w3.y, acc[r][1]);
                acc[r][2] = fmaf(a.w, w3.z, acc[r][2]);
                acc[r][3] = fmaf(a.w, w3.w, acc[r][3]);
            }
        }
        const float4 bv = *(const float4*)(o_b + tx * 4);
        #pragma unroll
        for (int r = 0; r < 8; ++r) {
            const int tok = wp * 8 + r, pi = tok >> 3, pj = tok & 7;
            const int rr = (wi * 8 + pi + SHIFT) & 255;
            const int cc = (wj * 8 + pj + SHIFT) & 255;
            float4 o;
            o.x = acc[r][0] + bv.x; o.y = acc[r][1] + bv.y;
            o.z = acc[r][2] + bv.z; o.w = acc[r][3] + bv.w;
            *(float4*)(out + (size_t)((((b << 8) + rr) << 8) + cc) * CH + tx * 4) = o;
        }
    }
}

extern "C" void kernel_launch(void* const* d_in, const int* in_sizes, int n_in,
                              void* d_out, int out_size)
{
    const float* x    = (const float*)d_in[0];
    const float* rpp  = (const float*)d_in[1];
    const float* wi_w = (const float*)d_in[2];
    const float* wi_b = (const float*)d_in[3];
    const float* w1_w = (const float*)d_in[4];
    const float* w1_b = (const float*)d_in[5];
    const float* w2_w = (const float*)d_in[6];
    const float* w2_b = (const float*)d_in[7];
    const float* q_w  = (const float*)d_in[8];
    const float* q_b  = (const float*)d_in[9];
    const float* kv_w = (const float*)d_in[10];
    const float* kv_b = (const float*)d_in[11];
    const float* o_w  = (const float*)d_in[12];
    const float* o_b  = (const float*)d_in[13];
    float* out = (float*)d_out;

    const size_t smem2 = (size_t)(4 * P2 * STR + 4096 + 256 + 256) * sizeof(float);
    cudaFuncSetAttribute(k_main, cudaFuncAttributeMaxDynamicSharedMemorySize, (int)smem2);

    k_prep<<<NWIN, 256>>>(x, wi_w, wi_b, w1_w, w1_b, w2_w, w2_b);
    k_main<<<NWIN, NTHR, smem2>>>(rpp, q_w, q_b, kv_w, kv_b, o_w, o_b, out);
}